// round 1
// baseline (speedup 1.0000x reference)
#include <cuda_runtime.h>

#define B 64
#define H 768
#define E 128

// Partials: S2 core-row sums (4 partials per i), GEMM k-split partials.
__device__ float g_S2p[512];
__device__ float g_P[3][12][B][E];   // [mat][ksplit][b][e], fully rewritten every launch

// ---------------------------------------------------------------------------
// K1: reduce core[128,128,128] -> 512 partial sums (4 per leading index i).
// Block p handles core[p*4096 .. p*4096+4096). 512 blocks x 256 threads,
// float4 loads, 4 per thread.
// ---------------------------------------------------------------------------
__global__ void k_core_reduce(const float* __restrict__ core) {
    const int p = blockIdx.x;
    const float4* src = reinterpret_cast<const float4*>(core) + (size_t)p * 1024;
    const int t = threadIdx.x;
    float s = 0.f;
#pragma unroll
    for (int j = 0; j < 4; j++) {
        float4 v = src[t + j * 256];
        s += (v.x + v.y) + (v.z + v.w);
    }
#pragma unroll
    for (int o = 16; o > 0; o >>= 1) s += __shfl_xor_sync(0xffffffffu, s, o);
    __shared__ float ws[8];
    if ((t & 31) == 0) ws[t >> 5] = s;
    __syncthreads();
    if (t == 0) {
        float tot = 0.f;
#pragma unroll
        for (int w = 0; w < 8; w++) tot += ws[w];
        g_S2p[p] = tot;
    }
}

// ---------------------------------------------------------------------------
// K2: fused triple GEMM (head = hs @ We^T, rel = rs @ Wr^T, tail = ts @ We^T).
// Grid (ksplit=12, echunk=8, bgroup=2) = 192 blocks, 256 threads.
// Block tile: 32 b x 16 e x 64 k. Thread tile: 2 b x 1 e x 3 mats.
// Smem tiles XOR-swizzled (k4 ^ (row & 7)) for conflict-free LDS.128.
// Writes fp32 partials to g_P (no atomics, no zero-init needed).
// ---------------------------------------------------------------------------
__global__ void k_gemm(const float* __restrict__ hs, const float* __restrict__ rs,
                       const float* __restrict__ ts, const float* __restrict__ we,
                       const float* __restrict__ wr) {
    __shared__ float4 s_src[3][32][18];  // [mat][b][k4 padded]
    __shared__ float4 s_w[2][16][18];    // [We/Wr][e][k4 padded]

    const int ks = blockIdx.x, ec = blockIdx.y, bg = blockIdx.z;
    const int tid = threadIdx.x;
    const int b0 = bg * 32, e0 = ec * 16;
    const int c0 = ks * 16;  // k offset in float4 units (K chunk = 64 floats)

    // --- load src tiles (32 rows x 16 float4 each), coalesced, swizzled store
    const float4* g0 = reinterpret_cast<const float4*>(hs);
    const float4* g1 = reinterpret_cast<const float4*>(rs);
    const float4* g2 = reinterpret_cast<const float4*>(ts);
#pragma unroll
    for (int i = tid; i < 512; i += 256) {
        const int row = i >> 4, c4 = i & 15;
        const size_t gidx = (size_t)(b0 + row) * 192 + c0 + c4;
        const int sc = c4 ^ (row & 7);
        s_src[0][row][sc] = g0[gidx];
        s_src[1][row][sc] = g1[gidx];
        s_src[2][row][sc] = g2[gidx];
    }
    // --- load W tiles (16 rows x 16 float4 each)
    {
        const int row = tid >> 4, c4 = tid & 15;
        const size_t gidx = (size_t)(e0 + row) * 192 + c0 + c4;
        const int sc = c4 ^ (row & 7);
        s_w[0][row][sc] = reinterpret_cast<const float4*>(we)[gidx];
        s_w[1][row][sc] = reinterpret_cast<const float4*>(wr)[gidx];
    }
    __syncthreads();

    // thread mapping: te fast (coalesced epilogue), tb slow
    const int te = tid & 15;   // e within tile
    const int tb = tid >> 4;   // b pair within tile
    const int ba = 2 * tb, bb = ba + 1;

    float h0 = 0.f, h1 = 0.f, r0 = 0.f, r1 = 0.f, t0 = 0.f, t1 = 0.f;
#pragma unroll
    for (int k4 = 0; k4 < 16; k4++) {
        const float4 vwe = s_w[0][te][k4 ^ (te & 7)];
        const float4 vwr = s_w[1][te][k4 ^ (te & 7)];
        const int sa = k4 ^ (ba & 7), sb = k4 ^ (bb & 7);
        float4 a, c;
        a = s_src[0][ba][sa]; c = s_src[0][bb][sb];
        h0 += vwe.x * a.x + vwe.y * a.y + vwe.z * a.z + vwe.w * a.w;
        h1 += vwe.x * c.x + vwe.y * c.y + vwe.z * c.z + vwe.w * c.w;
        a = s_src[1][ba][sa]; c = s_src[1][bb][sb];
        r0 += vwr.x * a.x + vwr.y * a.y + vwr.z * a.z + vwr.w * a.w;
        r1 += vwr.x * c.x + vwr.y * c.y + vwr.z * c.z + vwr.w * c.w;
        a = s_src[2][ba][sa]; c = s_src[2][bb][sb];
        t0 += vwe.x * a.x + vwe.y * a.y + vwe.z * a.z + vwe.w * a.w;
        t1 += vwe.x * c.x + vwe.y * c.y + vwe.z * c.z + vwe.w * c.w;
    }

    const int bga = b0 + ba, bgb = b0 + bb;
    const int e = e0 + te;
    g_P[0][ks][bga][e] = h0;  g_P[0][ks][bgb][e] = h1;
    g_P[1][ks][bga][e] = r0;  g_P[1][ks][bgb][e] = r1;
    g_P[2][ks][bga][e] = t0;  g_P[2][ks][bgb][e] = t1;
}

// ---------------------------------------------------------------------------
// K3: combine. energy[b] = -sum_e (h+b_e)(r+b_r)(t+b_e) * S2[e]
// 64 blocks (one per b) x 128 threads (one per e).
// ---------------------------------------------------------------------------
__global__ void k_combine(const float* __restrict__ be, const float* __restrict__ br,
                          float* __restrict__ out) {
    const int b = blockIdx.x, e = threadIdx.x;
    float h = 0.f, r = 0.f, t = 0.f;
#pragma unroll
    for (int ks = 0; ks < 12; ks++) {
        h += g_P[0][ks][b][e];
        r += g_P[1][ks][b][e];
        t += g_P[2][ks][b][e];
    }
    h += be[e]; t += be[e]; r += br[e];
    const float s2 = g_S2p[4 * e] + g_S2p[4 * e + 1] + g_S2p[4 * e + 2] + g_S2p[4 * e + 3];
    float v = h * r * t * s2;
#pragma unroll
    for (int o = 16; o > 0; o >>= 1) v += __shfl_xor_sync(0xffffffffu, v, o);
    __shared__ float ws[4];
    if ((e & 31) == 0) ws[e >> 5] = v;
    __syncthreads();
    if (e == 0) out[b] = -(ws[0] + ws[1] + ws[2] + ws[3]);
}

// ---------------------------------------------------------------------------
extern "C" void kernel_launch(void* const* d_in, const int* in_sizes, int n_in,
                              void* d_out, int out_size) {
    const float* head = (const float*)d_in[0];
    const float* rel  = (const float*)d_in[1];
    const float* tail = (const float*)d_in[2];
    const float* We   = (const float*)d_in[3];
    const float* be   = (const float*)d_in[4];
    const float* Wr   = (const float*)d_in[5];
    const float* br   = (const float*)d_in[6];
    const float* core = (const float*)d_in[7];
    float* out = (float*)d_out;

    k_core_reduce<<<512, 256>>>(core);
    k_gemm<<<dim3(12, 8, 2), 256>>>(head, rel, tail, We, Wr);
    k_combine<<<64, 128>>>(be, br, out);
}

// round 2
// speedup vs baseline: 1.1976x; 1.1976x over previous
#include <cuda_runtime.h>

#define B 64
#define H 768
#define E 128

#define NRED 512   // core-reduce blocks
#define NGEMM 192  // gemm blocks (12 ksplit x 8 echunk x 2 bgroup)

__device__ float g_S2p[NRED];        // core partial sums (4 per leading index i)
__device__ float g_P[3][12][B][E];   // [mat][ksplit][b][e] gemm partials

// ---------------------------------------------------------------------------
// Fused K1+K2: blocks [0,512) reduce core; blocks [512,704) do the triple GEMM.
// Overlaps the HBM-bound core read with the FMA-bound GEMM in a single wave.
// ---------------------------------------------------------------------------
__global__ void k_fused(const float* __restrict__ core,
                        const float* __restrict__ hs, const float* __restrict__ rs,
                        const float* __restrict__ ts, const float* __restrict__ we,
                        const float* __restrict__ wr) {
    __shared__ float4 s_src[3][32][18];  // gemm: [mat][b][k4 padded]
    __shared__ float4 s_w[2][16][18];    // gemm: [We/Wr][e][k4 padded]

    const int bid = blockIdx.x;
    const int tid = threadIdx.x;

    if (bid < NRED) {
        // ---- core reduction: 16 KB contiguous chunk per block.
        // Four EXPLICIT independent loads per thread to force MLP=4 in SASS.
        const float4* src = reinterpret_cast<const float4*>(core) + (size_t)bid * 1024;
        const float4 v0 = __ldg(src + tid);
        const float4 v1 = __ldg(src + tid + 256);
        const float4 v2 = __ldg(src + tid + 512);
        const float4 v3 = __ldg(src + tid + 768);
        float s = ((v0.x + v0.y) + (v0.z + v0.w))
                + ((v1.x + v1.y) + (v1.z + v1.w))
                + ((v2.x + v2.y) + (v2.z + v2.w))
                + ((v3.x + v3.y) + (v3.z + v3.w));
#pragma unroll
        for (int o = 16; o > 0; o >>= 1) s += __shfl_xor_sync(0xffffffffu, s, o);
        float* ws = reinterpret_cast<float*>(s_w);  // reuse smem as scratch
        if ((tid & 31) == 0) ws[tid >> 5] = s;
        __syncthreads();
        if (tid == 0) {
            float tot = 0.f;
#pragma unroll
            for (int w = 0; w < 8; w++) tot += ws[w];
            g_S2p[bid] = tot;
        }
        return;
    }

    // ---- triple GEMM: head = hs@We^T, rel = rs@Wr^T, tail = ts@We^T
    const int lin = bid - NRED;
    const int ks = lin % 12, ec = (lin / 12) & 7, bg = lin / 96;
    const int b0 = bg * 32, e0 = ec * 16;
    const int c0 = ks * 16;  // k offset in float4 units (K chunk = 64 floats)

    const float4* g0 = reinterpret_cast<const float4*>(hs);
    const float4* g1 = reinterpret_cast<const float4*>(rs);
    const float4* g2 = reinterpret_cast<const float4*>(ts);
#pragma unroll
    for (int i = tid; i < 512; i += 256) {
        const int row = i >> 4, c4 = i & 15;
        const size_t gidx = (size_t)(b0 + row) * 192 + c0 + c4;
        const int sc = c4 ^ (row & 7);
        s_src[0][row][sc] = g0[gidx];
        s_src[1][row][sc] = g1[gidx];
        s_src[2][row][sc] = g2[gidx];
    }
    {
        const int row = tid >> 4, c4 = tid & 15;
        const size_t gidx = (size_t)(e0 + row) * 192 + c0 + c4;
        const int sc = c4 ^ (row & 7);
        s_w[0][row][sc] = reinterpret_cast<const float4*>(we)[gidx];
        s_w[1][row][sc] = reinterpret_cast<const float4*>(wr)[gidx];
    }
    __syncthreads();

    const int te = tid & 15;   // e within tile (fast -> coalesced epilogue)
    const int tb = tid >> 4;   // b pair within tile
    const int ba = 2 * tb, bb = ba + 1;

    float h0 = 0.f, h1 = 0.f, r0 = 0.f, r1 = 0.f, t0 = 0.f, t1 = 0.f;
#pragma unroll
    for (int k4 = 0; k4 < 16; k4++) {
        const float4 vwe = s_w[0][te][k4 ^ (te & 7)];
        const float4 vwr = s_w[1][te][k4 ^ (te & 7)];
        const int sa = k4 ^ (ba & 7), sb = k4 ^ (bb & 7);
        float4 a, c;
        a = s_src[0][ba][sa]; c = s_src[0][bb][sb];
        h0 += vwe.x * a.x + vwe.y * a.y + vwe.z * a.z + vwe.w * a.w;
        h1 += vwe.x * c.x + vwe.y * c.y + vwe.z * c.z + vwe.w * c.w;
        a = s_src[1][ba][sa]; c = s_src[1][bb][sb];
        r0 += vwr.x * a.x + vwr.y * a.y + vwr.z * a.z + vwr.w * a.w;
        r1 += vwr.x * c.x + vwr.y * c.y + vwr.z * c.z + vwr.w * c.w;
        a = s_src[2][ba][sa]; c = s_src[2][bb][sb];
        t0 += vwe.x * a.x + vwe.y * a.y + vwe.z * a.z + vwe.w * a.w;
        t1 += vwe.x * c.x + vwe.y * c.y + vwe.z * c.z + vwe.w * c.w;
    }

    const int bga = b0 + ba, bgb = b0 + bb;
    const int e = e0 + te;
    g_P[0][ks][bga][e] = h0;  g_P[0][ks][bgb][e] = h1;
    g_P[1][ks][bga][e] = r0;  g_P[1][ks][bgb][e] = r1;
    g_P[2][ks][bga][e] = t0;  g_P[2][ks][bgb][e] = t1;
}

// ---------------------------------------------------------------------------
// K3: combine. energy[b] = -sum_e (h+b_e)(r+b_r)(t+b_e) * S2[e]
// ---------------------------------------------------------------------------
__global__ void k_combine(const float* __restrict__ be, const float* __restrict__ br,
                          float* __restrict__ out) {
    const int b = blockIdx.x, e = threadIdx.x;
    float h = 0.f, r = 0.f, t = 0.f;
#pragma unroll
    for (int ks = 0; ks < 12; ks++) {
        h += g_P[0][ks][b][e];
        r += g_P[1][ks][b][e];
        t += g_P[2][ks][b][e];
    }
    h += be[e]; t += be[e]; r += br[e];
    const float s2 = g_S2p[4 * e] + g_S2p[4 * e + 1] + g_S2p[4 * e + 2] + g_S2p[4 * e + 3];
    float v = h * r * t * s2;
#pragma unroll
    for (int o = 16; o > 0; o >>= 1) v += __shfl_xor_sync(0xffffffffu, v, o);
    __shared__ float ws[4];
    if ((e & 31) == 0) ws[e >> 5] = v;
    __syncthreads();
    if (e == 0) out[b] = -(ws[0] + ws[1] + ws[2] + ws[3]);
}

// ---------------------------------------------------------------------------
extern "C" void kernel_launch(void* const* d_in, const int* in_sizes, int n_in,
                              void* d_out, int out_size) {
    const float* head = (const float*)d_in[0];
    const float* rel  = (const float*)d_in[1];
    const float* tail = (const float*)d_in[2];
    const float* We   = (const float*)d_in[3];
    const float* be   = (const float*)d_in[4];
    const float* Wr   = (const float*)d_in[5];
    const float* br   = (const float*)d_in[6];
    const float* core = (const float*)d_in[7];
    float* out = (float*)d_out;

    k_fused<<<NRED + NGEMM, 256>>>(core, head, rel, tail, We, Wr);
    k_combine<<<64, 128>>>(be, br, out);
}